// round 8
// baseline (speedup 1.0000x reference)
#include <cuda_runtime.h>
#include <cstddef>
#include <cstdint>

#define HDIM 64
#define NMAX 100352
#define EU_MAX 3300000
#define EB_MAX 350000

// ---------------- scratch (static device globals; no allocation allowed) ----
__device__ float g_aggu[(size_t)NMAX * HDIM];
__device__ float g_aggb[(size_t)NMAX * HDIM];
__device__ float g_y1u[(size_t)NMAX * HDIM];
__device__ float g_y1b[(size_t)NMAX * HDIM];
__device__ float g_y2[(size_t)NMAX * 2 * HDIM];
__device__ float g_stats[5 * 128];     // per BN: [0..63]=sum, [64..127]=sumsq
__device__ int g_degu[NMAX], g_degb[NMAX];
__device__ int g_offu[NMAX], g_offb[NMAX];
__device__ int g_curu[NMAX], g_curb[NMAX];
__device__ int g_part[2048];
__device__ int g_csru[EU_MAX];
__device__ int g_csrb[EB_MAX];

// ================= CSR build ================================================
__global__ void zero_kernel(int* __restrict__ degu, int* __restrict__ degb,
                            float* __restrict__ stats, int N)
{
    int i = blockIdx.x * blockDim.x + threadIdx.x;
    int stride = gridDim.x * blockDim.x;
    for (int t = i; t < N; t += stride) { degu[t] = 0; degb[t] = 0; }
    if (i < 5 * 128) stats[i] = 0.0f;
}

__global__ void hist_kernel(const int* __restrict__ du, int EU,
                            const int* __restrict__ db, int EB,
                            int* __restrict__ degu, int* __restrict__ degb)
{
    long i = blockIdx.x * (long)blockDim.x + threadIdx.x;
    long stride = gridDim.x * (long)blockDim.x;
    long total = EU + EB;
    for (long t = i; t < total; t += stride) {
        if (t < EU) atomicAdd(&degu[__ldg(&du[t])], 1);
        else        atomicAdd(&degb[__ldg(&db[t - EU])], 1);
    }
}

__global__ void scan1_kernel(const int* __restrict__ degu,
                             const int* __restrict__ degb,
                             int* __restrict__ part, int N)
{
    const int* deg = blockIdx.y ? degb : degu;
    __shared__ int sm[1024];
    int idx = blockIdx.x * 1024 + threadIdx.x;
    int v = (idx < N) ? deg[idx] : 0;
    sm[threadIdx.x] = v;
    __syncthreads();
    for (int o = 512; o > 0; o >>= 1) {
        if (threadIdx.x < o) sm[threadIdx.x] += sm[threadIdx.x + o];
        __syncthreads();
    }
    if (threadIdx.x == 0) part[blockIdx.y * 1024 + blockIdx.x] = sm[0];
}

__global__ void scan2_kernel(int* __restrict__ part, int NB)
{
    int y = blockIdx.y;
    int t = threadIdx.x;
    __shared__ int sm[2][1024];
    int v = (t < NB) ? part[y * 1024 + t] : 0;
    int c = 0;
    sm[0][t] = v;
    __syncthreads();
    for (int o = 1; o < 1024; o <<= 1) {
        int n = c ^ 1;
        int val = sm[c][t];
        if (t >= o) val += sm[c][t - o];
        sm[n][t] = val;
        __syncthreads();
        c = n;
    }
    if (t < NB) part[y * 1024 + t] = sm[c][t] - v;
}

__global__ void scan3_kernel(const int* __restrict__ degu,
                             const int* __restrict__ degb,
                             const int* __restrict__ part,
                             int* __restrict__ offu, int* __restrict__ offb,
                             int* __restrict__ curu, int* __restrict__ curb,
                             int N)
{
    const int* deg = blockIdx.y ? degb : degu;
    int* offs = blockIdx.y ? offb : offu;
    int* curp = blockIdx.y ? curb : curu;
    int idx = blockIdx.x * 1024 + threadIdx.x;
    int t = threadIdx.x;
    __shared__ int sm[2][1024];
    int v = (idx < N) ? deg[idx] : 0;
    int c = 0;
    sm[0][t] = v;
    __syncthreads();
    for (int o = 1; o < 1024; o <<= 1) {
        int n = c ^ 1;
        int val = sm[c][t];
        if (t >= o) val += sm[c][t - o];
        sm[n][t] = val;
        __syncthreads();
        c = n;
    }
    int off = part[blockIdx.y * 1024 + blockIdx.x] + sm[c][t] - v;
    if (idx < N) { offs[idx] = off; curp[idx] = off; }
}

__global__ void fill_kernel(const int* __restrict__ du, const int* __restrict__ su, int EU,
                            const int* __restrict__ db, const int* __restrict__ sb, int EB,
                            int* __restrict__ curu, int* __restrict__ curb,
                            int* __restrict__ csru, int* __restrict__ csrb)
{
    long i = blockIdx.x * (long)blockDim.x + threadIdx.x;
    long stride = gridDim.x * (long)blockDim.x;
    long total = EU + EB;
    for (long t = i; t < total; t += stride) {
        if (t < EU) {
            int d = __ldg(&du[t]);
            int pos = atomicAdd(&curu[d], 1);
            csru[pos] = __ldg(&su[t]);
        } else {
            long tb = t - EU;
            int d = __ldg(&db[tb]);
            int pos = atomicAdd(&curb[d], 1);
            csrb[pos] = __ldg(&sb[tb]);
        }
    }
}

// ---------------- gather-aggregate (warp per dst) + fused (1+eps)*x ---------
__global__ void gather_kernel(const float* __restrict__ x,
                              const float* __restrict__ battr,
                              const int* __restrict__ offu, const int* __restrict__ degu,
                              const int* __restrict__ csru,
                              const int* __restrict__ offb, const int* __restrict__ degb,
                              const int* __restrict__ csrb,
                              const float* __restrict__ eps1,
                              const float* __restrict__ eps2,
                              float* __restrict__ aggu, float* __restrict__ aggb,
                              int N)
{
    int gw = (blockIdx.x * blockDim.x + threadIdx.x) >> 5;
    int lane = threadIdx.x & 31;
    if (gw >= N) return;
    bool up = (blockIdx.y == 0);
    const float* feat = up ? x : battr;
    const int* offs = up ? offu : offb;
    const int* deg  = up ? degu : degb;
    const int* csr  = up ? csru : csrb;
    float* agg = up ? aggu : aggb;
    float e = 1.0f + (up ? __ldg(eps1) : __ldg(eps2));

    int off = __ldg(&offs[gw]);
    int dg  = __ldg(&deg[gw]);
    float a0 = 0.f, a1 = 0.f;
    int i = 0;
    for (; i + 4 <= dg; i += 4) {
        int s0 = __ldg(&csr[off + i]);
        int s1 = __ldg(&csr[off + i + 1]);
        int s2 = __ldg(&csr[off + i + 2]);
        int s3 = __ldg(&csr[off + i + 3]);
        float u0 = __ldg(&feat[((size_t)s0 << 6) + lane]);
        float u1 = __ldg(&feat[((size_t)s1 << 6) + lane]);
        float u2 = __ldg(&feat[((size_t)s2 << 6) + lane]);
        float u3 = __ldg(&feat[((size_t)s3 << 6) + lane]);
        float v0 = __ldg(&feat[((size_t)s0 << 6) + lane + 32]);
        float v1 = __ldg(&feat[((size_t)s1 << 6) + lane + 32]);
        float v2 = __ldg(&feat[((size_t)s2 << 6) + lane + 32]);
        float v3 = __ldg(&feat[((size_t)s3 << 6) + lane + 32]);
        a0 += (u0 + u1) + (u2 + u3);
        a1 += (v0 + v1) + (v2 + v3);
    }
    for (; i < dg; i++) {
        int s0 = __ldg(&csr[off + i]);
        a0 += __ldg(&feat[((size_t)s0 << 6) + lane]);
        a1 += __ldg(&feat[((size_t)s0 << 6) + lane + 32]);
    }
    float b0 = e * __ldg(&x[((size_t)gw << 6) + lane]);
    float b1 = e * __ldg(&x[((size_t)gw << 6) + lane + 32]);
    agg[((size_t)gw << 6) + lane]      = a0 + b0;
    agg[((size_t)gw << 6) + lane + 32] = a1 + b1;
}

// ================= mma.sync tf32x3 GEMM =====================================
// Y[i][j] = sum_k act(A[i][k]) * W[k][j] + bias[j],  j in [0,64)
// act = AFF ? relu(BN-affine from stats, coeffs computed in-kernel) : identity
// fp32 accuracy via 3-term tf32 split: D = hiA*hiW + hiA*loW + loA*hiW.
// Tile: 128 rows x 64 cols, 256 threads (8 warps, 4 row x 2 col),
// warp = m32n32 = 2x4 atoms of m16n8k8.

__device__ __forceinline__ float trunc_tf32(float v) {
    return __uint_as_float(__float_as_uint(v) & 0xFFFFE000u);
}

__device__ __forceinline__ void mma_tf32(float* c, const uint32_t* a, const uint32_t* b) {
    asm volatile(
        "mma.sync.aligned.m16n8k8.row.col.f32.tf32.tf32.f32 "
        "{%0,%1,%2,%3}, {%4,%5,%6,%7}, {%8,%9}, {%0,%1,%2,%3};"
        : "+f"(c[0]), "+f"(c[1]), "+f"(c[2]), "+f"(c[3])
        : "r"(a[0]), "r"(a[1]), "r"(a[2]), "r"(a[3]), "r"(b[0]), "r"(b[1]));
}

struct GArg {
    const float* A;
    const float* W;
    const float* bias;
    const float* st0; const float* g0; const float* be0;
    const float* st1; const float* g1; const float* be1;
    float* Y;
    float* stats;
};

// dynamic shared layout (floats)
#define AST 40                        // As row stride
#define WST 68                        // Ws row stride
#define F_AHI 0
#define F_ALO (128 * AST)
#define F_WHI (2 * 128 * AST)
#define F_WLO (2 * 128 * AST + 32 * WST)
#define F_SRED (2 * 128 * AST + 2 * 32 * WST)
#define F_SC (F_SRED + 128)
static constexpr int SMEM_FLOATS_K64  = F_SC + 2 * 64;
static constexpr int SMEM_FLOATS_K128 = F_SC + 2 * 128;

template <int K, bool AFF>
__global__ __launch_bounds__(256)
void gemm_bn(GArg ga, GArg gb, int ldY, int N, float invN)
{
    extern __shared__ float smf[];
    float* AHI = smf + F_AHI;
    float* ALO = smf + F_ALO;
    float* WHI = smf + F_WHI;
    float* WLO = smf + F_WLO;
    float* SRED = smf + F_SRED;
    float* sSc = smf + F_SC;
    float* sSh = sSc + K;

    const GArg g = blockIdx.y ? gb : ga;
    const int tid  = threadIdx.x;
    const int lane = tid & 31;
    const int wid  = tid >> 5;
    const int wrow = wid >> 1;           // 0..3  (32 rows each)
    const int wcol = wid & 1;            // 0..1  (32 cols each)
    const int q    = lane & 3;           // quad lane
    const int lr4  = lane >> 2;          // 0..7
    const int rbase = blockIdx.x * 128;

    if (tid < 128) SRED[tid] = 0.0f;

    if (AFF) {
        if (tid < K) {
            const float* st = (tid < 64) ? g.st0 : g.st1;
            const float* gg = (tid < 64) ? g.g0  : g.g1;
            const float* bb = (tid < 64) ? g.be0 : g.be1;
            int j = tid & 63;
            float mean = st[j] * invN;
            float var  = st[64 + j] * invN - mean * mean;
            float s = gg[j] * rsqrtf(var + 1e-5f);
            sSc[tid] = s;
            sSh[tid] = bb[j] - mean * s;
        }
        __syncthreads();
    }

    float acc[2][4][4];
#pragma unroll
    for (int am = 0; am < 2; am++)
#pragma unroll
        for (int an = 0; an < 4; an++)
#pragma unroll
            for (int e = 0; e < 4; e++) acc[am][an][e] = 0.0f;

#pragma unroll
    for (int kc = 0; kc < K; kc += 32) {
        // --- stage A chunk (128 rows x 32 cols): affine, hi/lo split --------
#pragma unroll
        for (int it = 0; it < 4; it++) {
            int lin = it * 256 + tid;    // 1024 float4 slots
            int r   = lin >> 3;
            int c4  = (lin & 7) * 4;
            int gr  = rbase + r;
            float4 v = make_float4(0.f, 0.f, 0.f, 0.f);
            if (gr < N) v = *(const float4*)&g.A[(size_t)gr * K + kc + c4];
            if (AFF) {
                int c = kc + c4;
                float4 s = *(const float4*)&sSc[c];
                float4 h = *(const float4*)&sSh[c];
                v.x = fmaxf(v.x * s.x + h.x, 0.f);
                v.y = fmaxf(v.y * s.y + h.y, 0.f);
                v.z = fmaxf(v.z * s.z + h.z, 0.f);
                v.w = fmaxf(v.w * s.w + h.w, 0.f);
            }
            float4 hi, lo;
            hi.x = trunc_tf32(v.x); lo.x = v.x - hi.x;
            hi.y = trunc_tf32(v.y); lo.y = v.y - hi.y;
            hi.z = trunc_tf32(v.z); lo.z = v.z - hi.z;
            hi.w = trunc_tf32(v.w); lo.w = v.w - hi.w;
            *(float4*)&AHI[r * AST + c4] = hi;
            *(float4*)&ALO[r * AST + c4] = lo;
        }
        // --- stage W chunk (32 rows x 64 cols): hi/lo split -----------------
#pragma unroll
        for (int it = 0; it < 2; it++) {
            int lin = it * 256 + tid;    // 512 float4 slots
            int r   = lin >> 4;
            int c4  = (lin & 15) * 4;
            float4 v = *(const float4*)&g.W[(size_t)(kc + r) * 64 + c4];
            float4 hi, lo;
            hi.x = trunc_tf32(v.x); lo.x = v.x - hi.x;
            hi.y = trunc_tf32(v.y); lo.y = v.y - hi.y;
            hi.z = trunc_tf32(v.z); lo.z = v.z - hi.z;
            hi.w = trunc_tf32(v.w); lo.w = v.w - hi.w;
            *(float4*)&WHI[r * WST + c4] = hi;
            *(float4*)&WLO[r * WST + c4] = lo;
        }
        __syncthreads();

        // --- compute: 3 segments (hi*hi, hi*lo, lo*hi), 4 k-steps each ------
#pragma unroll
        for (int seg = 0; seg < 3; seg++) {
            const float* Ap = (seg == 2) ? ALO : AHI;
            const float* Wp = (seg == 1) ? WLO : WHI;
#pragma unroll
            for (int ks = 0; ks < 4; ks++) {
                int k0 = ks * 8;
                uint32_t b[4][2];
#pragma unroll
                for (int an = 0; an < 4; an++) {
                    int n = wcol * 32 + an * 8 + lr4;
                    b[an][0] = __float_as_uint(Wp[(k0 + q) * WST + n]);
                    b[an][1] = __float_as_uint(Wp[(k0 + q + 4) * WST + n]);
                }
#pragma unroll
                for (int am = 0; am < 2; am++) {
                    int r = wrow * 32 + am * 16 + lr4;
                    uint32_t a[4];
                    a[0] = __float_as_uint(Ap[r * AST + k0 + q]);
                    a[1] = __float_as_uint(Ap[(r + 8) * AST + k0 + q]);
                    a[2] = __float_as_uint(Ap[r * AST + k0 + q + 4]);
                    a[3] = __float_as_uint(Ap[(r + 8) * AST + k0 + q + 4]);
#pragma unroll
                    for (int an = 0; an < 4; an++)
                        mma_tf32(acc[am][an], a, b[an]);
                }
            }
        }
        __syncthreads();
    }

    // --- epilogue: bias, store, stats ----------------------------------------
    float psum[8], psq[8];
#pragma unroll
    for (int j = 0; j < 8; j++) { psum[j] = 0.f; psq[j] = 0.f; }

#pragma unroll
    for (int am = 0; am < 2; am++) {
        int r0 = rbase + wrow * 32 + am * 16 + lr4;
#pragma unroll
        for (int an = 0; an < 4; an++) {
            int colb = wcol * 32 + an * 8 + 2 * q;
            float2 bv = *(const float2*)&g.bias[colb];
            float v0 = acc[am][an][0] + bv.x;
            float v1 = acc[am][an][1] + bv.y;
            float v2 = acc[am][an][2] + bv.x;
            float v3 = acc[am][an][3] + bv.y;
            if (r0 < N) {
                *(float2*)&g.Y[(size_t)r0 * ldY + colb] = make_float2(v0, v1);
                psum[2 * an]     += v0;  psq[2 * an]     += v0 * v0;
                psum[2 * an + 1] += v1;  psq[2 * an + 1] += v1 * v1;
            }
            if (r0 + 8 < N) {
                *(float2*)&g.Y[(size_t)(r0 + 8) * ldY + colb] = make_float2(v2, v3);
                psum[2 * an]     += v2;  psq[2 * an]     += v2 * v2;
                psum[2 * an + 1] += v3;  psq[2 * an + 1] += v3 * v3;
            }
        }
    }
    // reduce over the 8 lanes sharing the same columns (lane>>2 varies)
#pragma unroll
    for (int j = 0; j < 8; j++) {
#pragma unroll
        for (int o = 4; o < 32; o <<= 1) {
            psum[j] += __shfl_xor_sync(0xFFFFFFFFu, psum[j], o);
            psq[j]  += __shfl_xor_sync(0xFFFFFFFFu, psq[j],  o);
        }
    }
    if (lr4 == 0) {
#pragma unroll
        for (int an = 0; an < 4; an++) {
            int colb = wcol * 32 + an * 8 + 2 * q;
            atomicAdd(&SRED[colb],          psum[2 * an]);
            atomicAdd(&SRED[colb + 1],      psum[2 * an + 1]);
            atomicAdd(&SRED[64 + colb],     psq[2 * an]);
            atomicAdd(&SRED[64 + colb + 1], psq[2 * an + 1]);
        }
    }
    __syncthreads();
    if (tid < 128) atomicAdd(&g.stats[tid], SRED[tid]);
}

// ================= final BN + ReLU (coeffs in-kernel) =======================
__global__ void bnrelu_kernel(float* __restrict__ Y,
                              const float* __restrict__ stats,
                              const float* __restrict__ g,
                              const float* __restrict__ be,
                              int total4, float invN)
{
    __shared__ float sc[64], sh[64];
    if (threadIdx.x < 64) {
        int j = threadIdx.x;
        float mean = stats[j] * invN;
        float var  = stats[64 + j] * invN - mean * mean;
        float s = g[j] * rsqrtf(var + 1e-5f);
        sc[j] = s;
        sh[j] = be[j] - mean * s;
    }
    __syncthreads();
    int i = blockIdx.x * blockDim.x + threadIdx.x;
    int stride = gridDim.x * blockDim.x;
    float4* y4 = (float4*)Y;
    for (int t = i; t < total4; t += stride) {
        int c = (t * 4) & 63;
        float4 v = y4[t];
        float4 s = *(const float4*)&sc[c];
        float4 h = *(const float4*)&sh[c];
        v.x = fmaxf(v.x * s.x + h.x, 0.f);
        v.y = fmaxf(v.y * s.y + h.y, 0.f);
        v.z = fmaxf(v.z * s.z + h.z, 0.f);
        v.w = fmaxf(v.w * s.w + h.w, 0.f);
        y4[t] = v;
    }
}

// ================= launch ===================================================
extern "C" void kernel_launch(void* const* d_in, const int* in_sizes, int n_in,
                              void* d_out, int out_size)
{
    const float* x     = (const float*)d_in[0];
    const float* battr = (const float*)d_in[1];
    const int*   upidx = (const int*)d_in[2];
    const int*   bidx  = (const int*)d_in[3];
    const float* eps1  = (const float*)d_in[4];
    const float* eps2  = (const float*)d_in[5];
    const float* uw1 = (const float*)d_in[6];
    const float* ub1 = (const float*)d_in[7];
    const float* ug1 = (const float*)d_in[8];
    const float* ube1= (const float*)d_in[9];
    const float* uw2 = (const float*)d_in[10];
    const float* ub2 = (const float*)d_in[11];
    const float* ug2 = (const float*)d_in[12];
    const float* ube2= (const float*)d_in[13];
    const float* bw1 = (const float*)d_in[14];
    const float* bb1 = (const float*)d_in[15];
    const float* bg1 = (const float*)d_in[16];
    const float* bbe1= (const float*)d_in[17];
    const float* bw2 = (const float*)d_in[18];
    const float* bb2 = (const float*)d_in[19];
    const float* bg2 = (const float*)d_in[20];
    const float* bbe2= (const float*)d_in[21];
    const float* cw  = (const float*)d_in[22];
    const float* cb  = (const float*)d_in[23];
    const float* cg  = (const float*)d_in[24];
    const float* cbe = (const float*)d_in[25];
    float* out = (float*)d_out;

    int N  = in_sizes[0] / HDIM;
    int EU = in_sizes[2] / 2;
    int EB = in_sizes[3] / 2;

    float *aggu, *aggb, *y1u, *y1b, *y2, *stats;
    int *degu, *degb, *offu, *offb, *curu, *curb, *part, *csru, *csrb;
    cudaGetSymbolAddress((void**)&aggu,  g_aggu);
    cudaGetSymbolAddress((void**)&aggb,  g_aggb);
    cudaGetSymbolAddress((void**)&y1u,   g_y1u);
    cudaGetSymbolAddress((void**)&y1b,   g_y1b);
    cudaGetSymbolAddress((void**)&y2,    g_y2);
    cudaGetSymbolAddress((void**)&stats, g_stats);
    cudaGetSymbolAddress((void**)&degu,  g_degu);
    cudaGetSymbolAddress((void**)&degb,  g_degb);
    cudaGetSymbolAddress((void**)&offu,  g_offu);
    cudaGetSymbolAddress((void**)&offb,  g_offb);
    cudaGetSymbolAddress((void**)&curu,  g_curu);
    cudaGetSymbolAddress((void**)&curb,  g_curb);
    cudaGetSymbolAddress((void**)&part,  g_part);
    cudaGetSymbolAddress((void**)&csru,  g_csru);
    cudaGetSymbolAddress((void**)&csrb,  g_csrb);

    int smem64  = SMEM_FLOATS_K64 * 4;
    int smem128 = SMEM_FLOATS_K128 * 4;
    cudaFuncSetAttribute(gemm_bn<64, false>,
                         cudaFuncAttributeMaxDynamicSharedMemorySize, smem64);
    cudaFuncSetAttribute(gemm_bn<64, true>,
                         cudaFuncAttributeMaxDynamicSharedMemorySize, smem64);
    cudaFuncSetAttribute(gemm_bn<128, true>,
                         cudaFuncAttributeMaxDynamicSharedMemorySize, smem128);

    float invN = 1.0f / (float)N;
    int total4 = (N * HDIM) / 4;
    int gb = (N + 127) / 128;
    int NB = (N + 1023) / 1024;

    const int* du = upidx;
    const int* su = upidx + EU;
    const int* db = bidx + EB;
    const int* sb = bidx;

    // Phase 0: CSR build
    zero_kernel<<<256, 256>>>(degu, degb, stats, N);
    hist_kernel<<<4096, 256>>>(du, EU, db, EB, degu, degb);
    scan1_kernel<<<dim3(NB, 2), 1024>>>(degu, degb, part, N);
    scan2_kernel<<<dim3(1, 2), 1024>>>(part, NB);
    scan3_kernel<<<dim3(NB, 2), 1024>>>(degu, degb, part, offu, offb, curu, curb, N);
    fill_kernel<<<4096, 256>>>(du, su, EU, db, sb, EB, curu, curb, csru, csrb);

    // Phase 1: gather-aggregate (fused (1+eps)*x self term)
    gather_kernel<<<dim3((N + 7) / 8, 2), 256>>>(
        x, battr, offu, degu, csru, offb, degb, csrb, eps1, eps2, aggu, aggb, N);

    // Phase 2: layer-1 GEMMs (mma.sync dual) + fused stats
    {
        GArg gu = { aggu, uw1, ub1, nullptr, nullptr, nullptr,
                    nullptr, nullptr, nullptr, y1u, stats + 0 };
        GArg gv = { aggb, bw1, bb1, nullptr, nullptr, nullptr,
                    nullptr, nullptr, nullptr, y1b, stats + 128 };
        gemm_bn<64, false><<<dim3(gb, 2), 256, smem64>>>(gu, gv, 64, N, invN);
    }

    // Phase 3: layer-2 GEMMs, input BN+ReLU from stats (in-kernel coeffs)
    {
        GArg gu = { y1u, uw2, ub2, stats + 0,   ug1, ube1,
                    stats + 0,   ug1, ube1, y2,      stats + 256 };
        GArg gv = { y1b, bw2, bb2, stats + 128, bg1, bbe1,
                    stats + 128, bg1, bbe1, y2 + 64, stats + 384 };
        gemm_bn<64, true><<<dim3(gb, 2), 256, smem64>>>(gu, gv, 128, N, invN);
    }

    // Phase 4: combine GEMM (K=128), input BN+ReLU from two stats sets
    {
        GArg gc = { y2, cw, cb, stats + 256, ug2, ube2,
                    stats + 384, bg2, bbe2, out, stats + 512 };
        gemm_bn<128, true><<<dim3(gb, 1), 256, smem128>>>(gc, gc, 64, N, invN);
    }

    // Phase 5: final BN+ReLU in place on out
    bnrelu_kernel<<<592, 256>>>(out, stats + 512, cg, cbe, total4, invN);
}